// round 10
// baseline (speedup 1.0000x reference)
#include <cuda_runtime.h>
#include <math.h>
#include <float.h>

// GaussianQuantRegularizer2 — fused codebook argmax + KL mean, single kernel.
// R10: R6 register-resident double-buffer (direct q[BUF][jj] access — the R7/R9
// pointer-cast forced q into local memory, doubling L1 traffic) + chunked
// deferred argmax: hot loop is FFMA2 + FMNMX only; winning 32-pair chunk is
// rescanned once with bit-identical op order for the exact first-max index.
//
// Identities: zhat == prior[idx] (STE cancels), kl_loss == mean(kl2)
// (ge+eq+le==1), argmax score == 16-dim dot f=[iv-1, mu*iv] . g_k=[-s^2/2, s].

#define THREADS 256
#define NPAIRS  512            // 1024 codes as 512 (even,odd) code-pairs
#define CHUNK   32             // pairs per argmax chunk
#define NCHUNK  (NPAIRS / CHUNK)
#define NB      256            // 65536 row-pairs / 256 threads
#define SMEM_ENT (NPAIRS * 16 + 16)  // u64 entries; +16 pad for tail prefetch
#define SMEM_BYTES (SMEM_ENT * 8)    // 65664

__device__ float g_partials[NB];
__device__ unsigned int g_done = 0;

static __device__ __forceinline__ unsigned long long pack2f(float lo, float hi) {
    unsigned long long r;
    asm("mov.b64 %0, {%1, %2};" : "=l"(r) : "f"(lo), "f"(hi));
    return r;
}
static __device__ __forceinline__ void unpack2f(unsigned long long v, float &lo, float &hi) {
    asm("mov.b64 {%0, %1}, %2;" : "=f"(lo), "=f"(hi) : "l"(v));
}
static __device__ __forceinline__ unsigned long long ffma2(unsigned long long a,
                                                           unsigned long long b,
                                                           unsigned long long c) {
    unsigned long long d;
    asm("fma.rn.f32x2 %0, %1, %2, %3;" : "=l"(d) : "l"(a), "l"(b), "l"(c));
    return d;
}
static __device__ __forceinline__ unsigned long long fmul2(unsigned long long a,
                                                           unsigned long long b) {
    unsigned long long d;
    asm("mul.rn.f32x2 %0, %1, %2;" : "=l"(d) : "l"(a), "l"(b));
    return d;
}
static __device__ __forceinline__ unsigned long long fadd2(unsigned long long a,
                                                           unsigned long long b) {
    unsigned long long d;
    asm("add.rn.f32x2 %0, %1, %2;" : "=l"(d) : "l"(a), "l"(b));
    return d;
}

// Score of one code-pair vs row R. QA must be a ulonglong2[8] lvalue (register
// array with constant indices after unroll). IDENTICAL op order everywhere.
#define GQR_SCORE(QA, R, SE, SO)                                           \
    do {                                                                   \
        unsigned long long a0 = fmul2(fp[R][0], (QA)[0].x);                \
        unsigned long long a1 = fmul2(fp[R][1], (QA)[0].y);                \
        _Pragma("unroll")                                                  \
        for (int jj = 1; jj < 8; jj++) {                                   \
            a0 = ffma2(fp[R][2 * jj],     (QA)[jj].x, a0);                 \
            a1 = ffma2(fp[R][2 * jj + 1], (QA)[jj].y, a1);                 \
        }                                                                  \
        unpack2f(fadd2(a0, a1), SE, SO);                                   \
    } while (0)

__global__ __launch_bounds__(THREADS, 2)
void gqr_main(const float* __restrict__ z, const float* __restrict__ prior,
              float* __restrict__ out, int nrows, long long idx_off,
              long long kl_off, float scale)
{
    // Codebook as u64 stream: entry (16*p + t) = (gA_t, gB_t) for code pair p,
    // feature t (0..7 quadratic -s^2/2, 8..15 linear s). A=code 2p, B=2p+1.
    extern __shared__ unsigned long long cbu[];

    for (int e = threadIdx.x; e < NPAIRS * 16; e += THREADS) {
        int p = e >> 4, t = e & 15;
        int k0 = p * 2, k1 = k0 + 1;
        float a, b;
        if (t < 8) {
            float x = prior[k0 * 8 + t]; a = -0.5f * x * x;
            float y = prior[k1 * 8 + t]; b = -0.5f * y * y;
        } else {
            a = prior[k0 * 8 + t - 8];
            b = prior[k1 * 8 + t - 8];
        }
        cbu[e] = pack2f(a, b);
    }
    if (threadIdx.x < 16) cbu[NPAIRS * 16 + threadIdx.x] = 0ULL;  // prefetch pad
    __syncthreads();

    int tt = blockIdx.x * THREADS + threadIdx.x;   // one row-PAIR per thread
    int npr = nrows >> 1;
    float klacc = 0.0f;

    if (tt < npr) {
        int n0 = tt << 1;
        int bb = n0 >> 12;          // H*W = 4096
        int hw = n0 & 4095;         // even -> rows n0, n0+1 share bb
        const float* zp = z + ((size_t)bb << 16) + hw;

        unsigned long long fp[2][16];   // fp[r][t] = (f_t, f_t)
        #pragma unroll
        for (int d = 0; d < 8; d++) {
            float2 mu2 = *(const float2*)(zp + ((size_t)d << 12));
            float2 lv2 = *(const float2*)(zp + ((size_t)(8 + d) << 12));
            #pragma unroll
            for (int r = 0; r < 2; r++) {
                float mu = r ? mu2.y : mu2.x;
                float lv = r ? lv2.y : lv2.x;
                lv = fminf(fmaxf(lv, -30.0f), 20.0f);
                float var = expf(lv);
                float iv  = 1.0f / var;
                fp[r][d]     = pack2f(iv - 1.0f, iv - 1.0f);
                float fl  = mu * iv;
                fp[r][8 + d] = pack2f(fl, fl);
                klacc += mu * mu + var - 1.0f - lv;
            }
        }

        float gbest0 = -FLT_MAX, gbest1 = -FLT_MAX;
        int   gch0 = 0, gch1 = 0;

        // double-buffered prefetch, registers only (direct constant indexing)
        ulonglong2 q[2][8];
        const ulonglong2* cp = (const ulonglong2*)cbu;
        #pragma unroll
        for (int jj = 0; jj < 8; jj++) q[0][jj] = cp[jj];

        for (int c = 0; c < NCHUNK; c++) {
            float cE0 = -FLT_MAX, cO0 = -FLT_MAX;
            float cE1 = -FLT_MAX, cO1 = -FLT_MAX;
            for (int pp = 0; pp < CHUNK; pp += 2) {
                {   // compute buf0, prefetch buf1
                    #pragma unroll
                    for (int jj = 0; jj < 8; jj++) q[1][jj] = cp[8 + jj];
                    float sE, sO;
                    GQR_SCORE(q[0], 0, sE, sO);
                    cE0 = fmaxf(cE0, sE); cO0 = fmaxf(cO0, sO);
                    GQR_SCORE(q[0], 1, sE, sO);
                    cE1 = fmaxf(cE1, sE); cO1 = fmaxf(cO1, sO);
                }
                {   // compute buf1, prefetch buf0 (pad covers final over-read)
                    #pragma unroll
                    for (int jj = 0; jj < 8; jj++) q[0][jj] = cp[16 + jj];
                    float sE, sO;
                    GQR_SCORE(q[1], 0, sE, sO);
                    cE0 = fmaxf(cE0, sE); cO0 = fmaxf(cO0, sO);
                    GQR_SCORE(q[1], 1, sE, sO);
                    cE1 = fmaxf(cE1, sE); cO1 = fmaxf(cO1, sO);
                }
                cp += 16;
            }
            float cm0 = fmaxf(cE0, cO0), cm1 = fmaxf(cE1, cO1);
            bool b0 = cm0 > gbest0, b1 = cm1 > gbest1;  // first chunk wins
            gbest0 = fmaxf(gbest0, cm0); gbest1 = fmaxf(gbest1, cm1);
            gch0 = b0 ? c : gch0; gch1 = b1 ? c : gch1;
        }

        // rescan winning chunk (bit-identical recompute) for exact first index
        float gbest[2] = { gbest0, gbest1 };
        int   gch[2]   = { gch0, gch1 };
        int   idx[2];
        #pragma unroll
        for (int r = 0; r < 2; r++) {
            const ulonglong2* rp = (const ulonglong2*)cbu + (size_t)gch[r] * CHUNK * 8;
            int found = 0;
            bool done = false;
            for (int p = 0; p < CHUNK && !done; p++) {
                ulonglong2 rq[8];
                #pragma unroll
                for (int jj = 0; jj < 8; jj++) rq[jj] = rp[p * 8 + jj];
                float sE, sO;
                GQR_SCORE(rq, r, sE, sO);
                if (sE == gbest[r])      { found = (gch[r] * CHUNK + p) * 2;     done = true; }
                else if (sO == gbest[r]) { found = (gch[r] * CHUNK + p) * 2 + 1; done = true; }
            }
            idx[r] = found;
        }

        const float* pvA = prior + (size_t)idx[0] * 8;
        const float* pvB = prior + (size_t)idx[1] * 8;
        #pragma unroll
        for (int d = 0; d < 8; d++) {
            float2 o; o.x = pvA[d]; o.y = pvB[d];
            *(float2*)(out + (((size_t)(bb * 8 + d)) << 12) + hw) = o;
        }
        out[idx_off + n0]     = (float)idx[0];
        out[idx_off + n0 + 1] = (float)idx[1];
    }

    // deterministic block-level KL partial
    #pragma unroll
    for (int o = 16; o > 0; o >>= 1)
        klacc += __shfl_down_sync(0xFFFFFFFFu, klacc, o);
    __shared__ float red[THREADS / 32];
    __shared__ int last_flag;
    if ((threadIdx.x & 31) == 0) red[threadIdx.x >> 5] = klacc;
    __syncthreads();
    if (threadIdx.x == 0) {
        float s = 0.0f;
        #pragma unroll
        for (int i = 0; i < THREADS / 32; i++) s += red[i];
        g_partials[blockIdx.x] = s;
        __threadfence();
        unsigned int old = atomicAdd(&g_done, 1u);
        last_flag = (old == (unsigned int)(NB - 1)) ? 1 : 0;
    }
    __syncthreads();

    // last block fuses the finalize: sums partials, writes kl, resets counter
    if (last_flag) {
        __threadfence();
        float s = 0.0f;
        for (int i = threadIdx.x; i < NB; i += THREADS) s += g_partials[i];
        #pragma unroll
        for (int o = 16; o > 0; o >>= 1)
            s += __shfl_down_sync(0xFFFFFFFFu, s, o);
        if ((threadIdx.x & 31) == 0) red[threadIdx.x >> 5] = s;
        __syncthreads();
        if (threadIdx.x == 0) {
            float acc = 0.0f;
            #pragma unroll
            for (int i = 0; i < THREADS / 32; i++) acc += red[i];
            out[kl_off] = acc * scale;
            g_done = 0;                 // reset for next graph replay
            __threadfence();
        }
    }
}

extern "C" void kernel_launch(void* const* d_in, const int* in_sizes, int n_in,
                              void* d_out, int out_size)
{
    const float* z     = (const float*)d_in[0];
    // d_in[1] (noise) is provably unused by the forward values.
    const float* prior = (const float*)d_in[2];
    float* out = (float*)d_out;

    int nrows = in_sizes[0] / 16;                       // 131072
    long long idx_off = (long long)out_size - (long long)nrows;
    if (idx_off < 1) idx_off = 1;
    long long kl_off  = idx_off - 1;

    float scale = (1.4426f * 0.5f) / (float)nrows;

    (void)cudaFuncSetAttribute(gqr_main,
                               cudaFuncAttributeMaxDynamicSharedMemorySize, SMEM_BYTES);
    gqr_main<<<NB, THREADS, SMEM_BYTES>>>(z, prior, out, nrows, idx_off,
                                          kl_off, scale);
}

// round 13
// speedup vs baseline: 1.4928x; 1.4928x over previous
#include <cuda_runtime.h>
#include <math.h>
#include <float.h>

// GaussianQuantRegularizer2 — fused codebook argmax + KL mean, single kernel.
// R11: exact R6 hot-loop shape (register double-buffer, per-pair fmaxf+SEL
// select — the only shape ptxas compiles without local-memory spills) widened
// from 2 to 4 pipeline steps per iteration for a larger scheduling window.
// R9/R10 lesson: nothing after the hot loop may keep fp alive (rescan ⇒ spills).
//
// Identities: zhat == prior[idx] (STE cancels), kl_loss == mean(kl2)
// (ge+eq+le==1), argmax score == 16-dim dot f=[iv-1, mu*iv] . g_k=[-s^2/2, s].

#define THREADS 256
#define NPAIRS  512            // 1024 codes as 512 (even,odd) code-pairs
#define NB      256            // 65536 row-pairs / 256 threads
#define SMEM_ENT (NPAIRS * 16 + 16)  // u64 entries; +16 pad for tail prefetch
#define SMEM_BYTES (SMEM_ENT * 8)    // 65664

__device__ float g_partials[NB];
__device__ unsigned int g_done = 0;

static __device__ __forceinline__ unsigned long long pack2f(float lo, float hi) {
    unsigned long long r;
    asm("mov.b64 %0, {%1, %2};" : "=l"(r) : "f"(lo), "f"(hi));
    return r;
}
static __device__ __forceinline__ void unpack2f(unsigned long long v, float &lo, float &hi) {
    asm("mov.b64 {%0, %1}, %2;" : "=f"(lo), "=f"(hi) : "l"(v));
}
static __device__ __forceinline__ unsigned long long ffma2(unsigned long long a,
                                                           unsigned long long b,
                                                           unsigned long long c) {
    unsigned long long d;
    asm("fma.rn.f32x2 %0, %1, %2, %3;" : "=l"(d) : "l"(a), "l"(b), "l"(c));
    return d;
}
static __device__ __forceinline__ unsigned long long fmul2(unsigned long long a,
                                                           unsigned long long b) {
    unsigned long long d;
    asm("mul.rn.f32x2 %0, %1, %2;" : "=l"(d) : "l"(a), "l"(b));
    return d;
}
static __device__ __forceinline__ unsigned long long fadd2(unsigned long long a,
                                                           unsigned long long b) {
    unsigned long long d;
    asm("add.rn.f32x2 %0, %1, %2;" : "=l"(d) : "l"(a), "l"(b));
    return d;
}

__global__ __launch_bounds__(THREADS, 2)
void gqr_main(const float* __restrict__ z, const float* __restrict__ prior,
              float* __restrict__ out, int nrows, long long idx_off,
              long long kl_off, float scale)
{
    // Codebook as u64 stream: entry (16*p + t) = (gA_t, gB_t) for code pair p,
    // feature t (0..7 quadratic -s^2/2, 8..15 linear s). A=code 2p, B=2p+1.
    extern __shared__ unsigned long long cbu[];

    for (int e = threadIdx.x; e < NPAIRS * 16; e += THREADS) {
        int p = e >> 4, t = e & 15;
        int k0 = p * 2, k1 = k0 + 1;
        float a, b;
        if (t < 8) {
            float x = prior[k0 * 8 + t]; a = -0.5f * x * x;
            float y = prior[k1 * 8 + t]; b = -0.5f * y * y;
        } else {
            a = prior[k0 * 8 + t - 8];
            b = prior[k1 * 8 + t - 8];
        }
        cbu[e] = pack2f(a, b);
    }
    if (threadIdx.x < 16) cbu[NPAIRS * 16 + threadIdx.x] = 0ULL;  // prefetch pad
    __syncthreads();

    int tt = blockIdx.x * THREADS + threadIdx.x;   // one row-PAIR per thread
    int npr = nrows >> 1;
    float klacc = 0.0f;

    if (tt < npr) {
        int n0 = tt << 1;
        int bb = n0 >> 12;          // H*W = 4096
        int hw = n0 & 4095;         // even -> rows n0, n0+1 share bb
        const float* zp = z + ((size_t)bb << 16) + hw;

        unsigned long long fp[2][16];   // fp[r][t] = (f_t, f_t)
        #pragma unroll
        for (int d = 0; d < 8; d++) {
            float2 mu2 = *(const float2*)(zp + ((size_t)d << 12));
            float2 lv2 = *(const float2*)(zp + ((size_t)(8 + d) << 12));
            #pragma unroll
            for (int r = 0; r < 2; r++) {
                float mu = r ? mu2.y : mu2.x;
                float lv = r ? lv2.y : lv2.x;
                lv = fminf(fmaxf(lv, -30.0f), 20.0f);
                float var = expf(lv);
                float iv  = 1.0f / var;
                fp[r][d]     = pack2f(iv - 1.0f, iv - 1.0f);
                float fl  = mu * iv;
                fp[r][8 + d] = pack2f(fl, fl);
                klacc += mu * mu + var - 1.0f - lv;
            }
        }

        float bestE[2] = { -FLT_MAX, -FLT_MAX };
        float bestO[2] = { -FLT_MAX, -FLT_MAX };
        int   pE[2] = { 0, 0 }, pO[2] = { 0, 0 };

        // double-buffered prefetch: q[buf] computes while q[buf^1] loads next
        ulonglong2 q[2][8];
        const ulonglong2* cp = (const ulonglong2*)cbu;
        #pragma unroll
        for (int jj = 0; jj < 8; jj++) q[0][jj] = cp[jj];

        #define GQR_STEP(BUF, POFF)                                            \
        do {                                                                   \
            _Pragma("unroll")                                                  \
            for (int jj = 0; jj < 8; jj++)                                     \
                q[(BUF) ^ 1][jj] = cp[8 * ((POFF) + 1) + jj];                  \
            _Pragma("unroll")                                                  \
            for (int r = 0; r < 2; r++) {                                      \
                unsigned long long a0 = fmul2(fp[r][0], q[BUF][0].x);          \
                unsigned long long a1 = fmul2(fp[r][1], q[BUF][0].y);          \
                _Pragma("unroll")                                              \
                for (int jj = 1; jj < 8; jj++) {                               \
                    a0 = ffma2(fp[r][2 * jj],     q[BUF][jj].x, a0);           \
                    a1 = ffma2(fp[r][2 * jj + 1], q[BUF][jj].y, a1);           \
                }                                                              \
                float s0, s1;                                                  \
                unpack2f(fadd2(a0, a1), s0, s1);                               \
                bool g0 = s0 > bestE[r];                                       \
                bool g1 = s1 > bestO[r];                                       \
                bestE[r] = fmaxf(bestE[r], s0);                                \
                bestO[r] = fmaxf(bestO[r], s1);                                \
                pE[r] = g0 ? (p + (POFF)) : pE[r];                             \
                pO[r] = g1 ? (p + (POFF)) : pO[r];                             \
            }                                                                  \
        } while (0)

        for (int p = 0; p < NPAIRS; p += 4) {
            GQR_STEP(0, 0);
            GQR_STEP(1, 1);
            GQR_STEP(0, 2);
            GQR_STEP(1, 3);
            cp += 32;
        }
        #undef GQR_STEP

        int idx[2];
        #pragma unroll
        for (int r = 0; r < 2; r++) {
            int ie = 2 * pE[r], io = 2 * pO[r] + 1;
            if (bestO[r] > bestE[r])      idx[r] = io;
            else if (bestO[r] < bestE[r]) idx[r] = ie;
            else                          idx[r] = min(ie, io);  // first-max tie
        }

        const float* pvA = prior + (size_t)idx[0] * 8;
        const float* pvB = prior + (size_t)idx[1] * 8;
        #pragma unroll
        for (int d = 0; d < 8; d++) {
            float2 o; o.x = pvA[d]; o.y = pvB[d];
            *(float2*)(out + (((size_t)(bb * 8 + d)) << 12) + hw) = o;
        }
        out[idx_off + n0]     = (float)idx[0];
        out[idx_off + n0 + 1] = (float)idx[1];
    }

    // deterministic block-level KL partial
    #pragma unroll
    for (int o = 16; o > 0; o >>= 1)
        klacc += __shfl_down_sync(0xFFFFFFFFu, klacc, o);
    __shared__ float red[THREADS / 32];
    __shared__ int last_flag;
    if ((threadIdx.x & 31) == 0) red[threadIdx.x >> 5] = klacc;
    __syncthreads();
    if (threadIdx.x == 0) {
        float s = 0.0f;
        #pragma unroll
        for (int i = 0; i < THREADS / 32; i++) s += red[i];
        g_partials[blockIdx.x] = s;
        __threadfence();
        unsigned int old = atomicAdd(&g_done, 1u);
        last_flag = (old == (unsigned int)(NB - 1)) ? 1 : 0;
    }
    __syncthreads();

    // last block fuses the finalize: sums partials, writes kl, resets counter
    if (last_flag) {
        __threadfence();
        float s = 0.0f;
        for (int i = threadIdx.x; i < NB; i += THREADS) s += g_partials[i];
        #pragma unroll
        for (int o = 16; o > 0; o >>= 1)
            s += __shfl_down_sync(0xFFFFFFFFu, s, o);
        if ((threadIdx.x & 31) == 0) red[threadIdx.x >> 5] = s;
        __syncthreads();
        if (threadIdx.x == 0) {
            float acc = 0.0f;
            #pragma unroll
            for (int i = 0; i < THREADS / 32; i++) acc += red[i];
            out[kl_off] = acc * scale;
            g_done = 0;                 // reset for next graph replay
            __threadfence();
        }
    }
}

extern "C" void kernel_launch(void* const* d_in, const int* in_sizes, int n_in,
                              void* d_out, int out_size)
{
    const float* z     = (const float*)d_in[0];
    // d_in[1] (noise) is provably unused by the forward values.
    const float* prior = (const float*)d_in[2];
    float* out = (float*)d_out;

    int nrows = in_sizes[0] / 16;                       // 131072
    long long idx_off = (long long)out_size - (long long)nrows;
    if (idx_off < 1) idx_off = 1;
    long long kl_off  = idx_off - 1;

    float scale = (1.4426f * 0.5f) / (float)nrows;

    (void)cudaFuncSetAttribute(gqr_main,
                               cudaFuncAttributeMaxDynamicSharedMemorySize, SMEM_BYTES);
    gqr_main<<<NB, THREADS, SMEM_BYTES>>>(z, prior, out, nrows, idx_off,
                                          kl_off, scale);
}

// round 15
// speedup vs baseline: 1.8201x; 1.2193x over previous
#include <cuda_runtime.h>
#include <cuda_bf16.h>
#include <math.h>
#include <float.h>
#include <stdint.h>

// GaussianQuantRegularizer2 — R15: mma.sync (HMMA) tensor path.
// tcgen05 is unavailable (harness targets plain sm_100), but sm_80-era
// mma.sync.m16n8k16 bf16 compiles and runs on Blackwell's fallback HMMA path.
// Score S[row, code] = F[row,16] . G[code,16] computed as 6 bf16 cross-product
// MMAs (3-way operand splits, fp32 accum => ~2^-23 residual, far below the
// fp32-reorder noise already proven safe). Accumulators stay in registers, so
// argmax is register compares + one quad shfl merge. KL/finalize unchanged.
//
// Identities: zhat == prior[idx] (STE cancels), kl_loss == mean(kl2),
// argmax score == 16-dim dot f=[iv-1, mu*iv] . g_k=[-s^2/2, s].

#define THREADS 256            // 8 warps x 16 rows = 128 rows per CTA
#define NBLK    1024           // 131072 / 128
#define NCODES  1024
#define NTILE   (NCODES / 8)   // 128 code tiles of n=8

// smem layout (bytes)
#define SM_A1   0              // A splits: 128 rows x 16 bf16 = 4096 each
#define SM_A2   4096
#define SM_A3   8192
#define SM_B1   12288          // B splits: 1024 codes x 16 bf16 = 32768 each
#define SM_B2   45056
#define SM_B3   77824
#define SM_IDX  110592         // int idx[128]
#define SM_RED  111104         // float red[8]
#define SM_FLAG 111136
#define SM_TOTAL 111168

__device__ float g_partials[NBLK];
__device__ unsigned int g_done = 0;

static __device__ __forceinline__ void mma_bf16(float c[4],
        uint32_t a0, uint32_t a1, uint32_t a2, uint32_t a3,
        uint32_t b0, uint32_t b1) {
    asm volatile(
        "mma.sync.aligned.m16n8k16.row.col.f32.bf16.bf16.f32 "
        "{%0,%1,%2,%3}, {%4,%5,%6,%7}, {%8,%9}, {%0,%1,%2,%3};"
        : "+f"(c[0]), "+f"(c[1]), "+f"(c[2]), "+f"(c[3])
        : "r"(a0), "r"(a1), "r"(a2), "r"(a3), "r"(b0), "r"(b1));
}

static __device__ __forceinline__ void split3(float v, __nv_bfloat16& h1,
                                              __nv_bfloat16& h2, __nv_bfloat16& h3) {
    h1 = __float2bfloat16_rn(v);
    float r1 = v - __bfloat162float(h1);
    h2 = __float2bfloat16_rn(r1);
    float r2 = r1 - __bfloat162float(h2);
    h3 = __float2bfloat16_rn(r2);
}

static __device__ __forceinline__ void qmerge(float& b, int& i, int off) {
    float ob = __shfl_xor_sync(0xFFFFFFFFu, b, off);
    int   oi = __shfl_xor_sync(0xFFFFFFFFu, i, off);
    if (ob > b || (ob == b && oi < i)) { b = ob; i = oi; }
}

__global__ __launch_bounds__(THREADS, 2)
void gqr_mma(const float* __restrict__ z, const float* __restrict__ prior,
             float* __restrict__ out, int nrows, long long idx_off,
             long long kl_off, float scale)
{
    extern __shared__ char smem[];
    const int tid  = threadIdx.x;
    const int wid  = tid >> 5;
    const int lane = tid & 31;
    const int g    = lane >> 2;      // groupID (row within fragment)
    const int t4   = lane & 3;       // threadID_in_group

    // ---- codebook features -> 3-way bf16 split -> B1/B2/B3 (k-contiguous) --
    for (int e = tid; e < NCODES * 16; e += THREADS) {
        int c = e >> 4, k = e & 15;
        float s = prior[c * 8 + (k & 7)];
        float v = (k < 8) ? (-0.5f * s * s) : s;
        __nv_bfloat16 h1, h2, h3; split3(v, h1, h2, h3);
        uint32_t off = (uint32_t)(c * 32 + k * 2);
        *(__nv_bfloat16*)(smem + SM_B1 + off) = h1;
        *(__nv_bfloat16*)(smem + SM_B2 + off) = h2;
        *(__nv_bfloat16*)(smem + SM_B3 + off) = h3;
    }

    // ---- row features (threads 0..127, one row each) + KL ----
    float klacc = 0.0f;
    if (tid < 128) {
        int n  = blockIdx.x * 128 + tid;
        int bb = n >> 12, hw = n & 4095;
        const float* zp = z + ((size_t)bb << 16) + hw;
        #pragma unroll
        for (int d = 0; d < 8; d++) {
            float mu = zp[(size_t)d << 12];
            float lv = zp[(size_t)(8 + d) << 12];
            lv = fminf(fmaxf(lv, -30.0f), 20.0f);
            float var = expf(lv);
            float iv  = 1.0f / var;
            float fq  = iv - 1.0f;
            float fl  = mu * iv;
            klacc += mu * mu + var - 1.0f - lv;
            uint32_t oq = (uint32_t)(tid * 32 + d * 2);
            uint32_t ol = (uint32_t)(tid * 32 + (8 + d) * 2);
            __nv_bfloat16 h1, h2, h3;
            split3(fq, h1, h2, h3);
            *(__nv_bfloat16*)(smem + SM_A1 + oq) = h1;
            *(__nv_bfloat16*)(smem + SM_A2 + oq) = h2;
            *(__nv_bfloat16*)(smem + SM_A3 + oq) = h3;
            split3(fl, h1, h2, h3);
            *(__nv_bfloat16*)(smem + SM_A1 + ol) = h1;
            *(__nv_bfloat16*)(smem + SM_A2 + ol) = h2;
            *(__nv_bfloat16*)(smem + SM_A3 + ol) = h3;
        }
    }
    __syncthreads();

    // ---- A fragments (PTX m16n8k16 mapping), loaded once per warp ----
    // a0: row g, k=2t..2t+1 ; a1: row g+8 ; a2: row g, k+8 ; a3: row g+8, k+8
    const int R = wid * 16;
    uint32_t a1f[4], a2f[4], a3f[4];
    {
        uint32_t lo0 = (uint32_t)((R + g) * 32 + t4 * 4);
        uint32_t lo1 = (uint32_t)((R + g + 8) * 32 + t4 * 4);
        a1f[0] = *(const uint32_t*)(smem + SM_A1 + lo0);
        a1f[1] = *(const uint32_t*)(smem + SM_A1 + lo1);
        a1f[2] = *(const uint32_t*)(smem + SM_A1 + lo0 + 16);
        a1f[3] = *(const uint32_t*)(smem + SM_A1 + lo1 + 16);
        a2f[0] = *(const uint32_t*)(smem + SM_A2 + lo0);
        a2f[1] = *(const uint32_t*)(smem + SM_A2 + lo1);
        a2f[2] = *(const uint32_t*)(smem + SM_A2 + lo0 + 16);
        a2f[3] = *(const uint32_t*)(smem + SM_A2 + lo1 + 16);
        a3f[0] = *(const uint32_t*)(smem + SM_A3 + lo0);
        a3f[1] = *(const uint32_t*)(smem + SM_A3 + lo1);
        a3f[2] = *(const uint32_t*)(smem + SM_A3 + lo0 + 16);
        a3f[3] = *(const uint32_t*)(smem + SM_A3 + lo1 + 16);
    }

    // ---- main loop: 128 code tiles (n=8), two tiles in flight ----
    float best0 = -FLT_MAX, best1 = -FLT_MAX;
    int   idx0 = 0, idx1 = 0;
    const uint32_t boff = (uint32_t)(g * 32 + t4 * 4);  // b0 addr within tile

    for (int ct = 0; ct < NTILE; ct += 2) {
        uint32_t o0 = (uint32_t)ct * 256 + boff;
        uint32_t o1 = o0 + 256;
        uint32_t x10 = *(const uint32_t*)(smem + SM_B1 + o0);
        uint32_t x11 = *(const uint32_t*)(smem + SM_B1 + o0 + 16);
        uint32_t x20 = *(const uint32_t*)(smem + SM_B2 + o0);
        uint32_t x21 = *(const uint32_t*)(smem + SM_B2 + o0 + 16);
        uint32_t x30 = *(const uint32_t*)(smem + SM_B3 + o0);
        uint32_t x31 = *(const uint32_t*)(smem + SM_B3 + o0 + 16);
        uint32_t y10 = *(const uint32_t*)(smem + SM_B1 + o1);
        uint32_t y11 = *(const uint32_t*)(smem + SM_B1 + o1 + 16);
        uint32_t y20 = *(const uint32_t*)(smem + SM_B2 + o1);
        uint32_t y21 = *(const uint32_t*)(smem + SM_B2 + o1 + 16);
        uint32_t y30 = *(const uint32_t*)(smem + SM_B3 + o1);
        uint32_t y31 = *(const uint32_t*)(smem + SM_B3 + o1 + 16);

        float cA[4] = {0.f, 0.f, 0.f, 0.f};
        float cB[4] = {0.f, 0.f, 0.f, 0.f};
        // S = F1G1 + F1G2 + F2G1 + F2G2 + F1G3 + F3G1  (residual ~2^-23)
        mma_bf16(cA, a1f[0], a1f[1], a1f[2], a1f[3], x10, x11);
        mma_bf16(cB, a1f[0], a1f[1], a1f[2], a1f[3], y10, y11);
        mma_bf16(cA, a1f[0], a1f[1], a1f[2], a1f[3], x20, x21);
        mma_bf16(cB, a1f[0], a1f[1], a1f[2], a1f[3], y20, y21);
        mma_bf16(cA, a2f[0], a2f[1], a2f[2], a2f[3], x10, x11);
        mma_bf16(cB, a2f[0], a2f[1], a2f[2], a2f[3], y10, y11);
        mma_bf16(cA, a2f[0], a2f[1], a2f[2], a2f[3], x20, x21);
        mma_bf16(cB, a2f[0], a2f[1], a2f[2], a2f[3], y20, y21);
        mma_bf16(cA, a1f[0], a1f[1], a1f[2], a1f[3], x30, x31);
        mma_bf16(cB, a1f[0], a1f[1], a1f[2], a1f[3], y30, y31);
        mma_bf16(cA, a3f[0], a3f[1], a3f[2], a3f[3], x10, x11);
        mma_bf16(cB, a3f[0], a3f[1], a3f[2], a3f[3], y10, y11);

        // C mapping: c0 -> (row g, col 2t), c1 -> col 2t+1; c2,c3 -> row g+8
        int colA = ct * 8 + 2 * t4;
        int colB = colA + 8;
        bool q;
        q = cA[0] > best0; best0 = fmaxf(best0, cA[0]); idx0 = q ? colA     : idx0;
        q = cA[1] > best0; best0 = fmaxf(best0, cA[1]); idx0 = q ? colA + 1 : idx0;
        q = cA[2] > best1; best1 = fmaxf(best1, cA[2]); idx1 = q ? colA     : idx1;
        q = cA[3] > best1; best1 = fmaxf(best1, cA[3]); idx1 = q ? colA + 1 : idx1;
        q = cB[0] > best0; best0 = fmaxf(best0, cB[0]); idx0 = q ? colB     : idx0;
        q = cB[1] > best0; best0 = fmaxf(best0, cB[1]); idx0 = q ? colB + 1 : idx0;
        q = cB[2] > best1; best1 = fmaxf(best1, cB[2]); idx1 = q ? colB     : idx1;
        q = cB[3] > best1; best1 = fmaxf(best1, cB[3]); idx1 = q ? colB + 1 : idx1;
    }

    // ---- quad merge (cols are disjoint across the 4 lanes of a group) ----
    qmerge(best0, idx0, 1); qmerge(best0, idx0, 2);
    qmerge(best1, idx1, 1); qmerge(best1, idx1, 2);

    int* smidx = (int*)(smem + SM_IDX);
    if (t4 == 0) {
        smidx[R + g]     = idx0;     // row R+g
        smidx[R + g + 8] = idx1;     // row R+g+8
    }
    __syncwarp();

    // ---- outputs: zhat gather + indices (warp-local rows) ----
    {
        int r    = lane & 15;
        int half = lane >> 4;
        int n    = blockIdx.x * 128 + R + r;
        int bb   = n >> 12, hw = n & 4095;
        int mi   = smidx[R + r];
        if (half == 0) out[idx_off + n] = (float)mi;
        #pragma unroll
        for (int dd = 0; dd < 4; dd++) {
            int d = dd * 2 + half;
            out[(((size_t)(bb * 8 + d)) << 12) + hw] = prior[mi * 8 + d];
        }
    }

    // ---- KL block partial + fused last-block finalize ----
    #pragma unroll
    for (int o = 16; o > 0; o >>= 1)
        klacc += __shfl_down_sync(0xFFFFFFFFu, klacc, o);
    float* red   = (float*)(smem + SM_RED);
    int*   flagp = (int*)(smem + SM_FLAG);
    if (lane == 0) red[wid] = klacc;
    __syncthreads();
    if (tid == 0) {
        float s = 0.0f;
        #pragma unroll
        for (int i = 0; i < 8; i++) s += red[i];
        g_partials[blockIdx.x] = s;
        __threadfence();
        unsigned int old = atomicAdd(&g_done, 1u);
        *flagp = (old == (unsigned int)(NBLK - 1)) ? 1 : 0;
    }
    __syncthreads();
    if (*flagp) {
        __threadfence();
        float s = 0.0f;
        for (int i = tid; i < NBLK; i += THREADS) s += g_partials[i];
        #pragma unroll
        for (int o = 16; o > 0; o >>= 1)
            s += __shfl_down_sync(0xFFFFFFFFu, s, o);
        if (lane == 0) red[wid] = s;
        __syncthreads();
        if (tid == 0) {
            float acc = 0.0f;
            #pragma unroll
            for (int i = 0; i < 8; i++) acc += red[i];
            out[kl_off] = acc * scale;
            g_done = 0;
            __threadfence();
        }
    }
}

extern "C" void kernel_launch(void* const* d_in, const int* in_sizes, int n_in,
                              void* d_out, int out_size)
{
    const float* z     = (const float*)d_in[0];
    // d_in[1] (noise) is provably unused by the forward values.
    const float* prior = (const float*)d_in[2];
    float* out = (float*)d_out;

    int nrows = in_sizes[0] / 16;                       // 131072
    long long idx_off = (long long)out_size - (long long)nrows;
    if (idx_off < 1) idx_off = 1;
    long long kl_off  = idx_off - 1;

    float scale = (1.4426f * 0.5f) / (float)nrows;

    (void)cudaFuncSetAttribute(gqr_mma,
                               cudaFuncAttributeMaxDynamicSharedMemorySize, SM_TOTAL);
    gqr_mma<<<NBLK, THREADS, SM_TOTAL>>>(z, prior, out, nrows, idx_off,
                                         kl_off, scale);
}